// round 15
// baseline (speedup 1.0000x reference)
#include <cuda_runtime.h>

// ShortConv1D: causal depthwise conv1d
// x: [B=4, S=4096, D=2048] f32, w: [D, K=4], b: [D]
// out[b,t,d] = b[d] + sum_k w[d,k] * x[b, t+k-(K-1), d]
//
// R14: FRACTIONAL L2 pinning of x.
// R10 (evict_last fraction=1.0) barely helped: x (128MB) > L2 (126MB), so the
// pinned class itself thrashes at the capacity margin. The fractional policy
// is address-hashed and deterministic: fraction=0.85 pins the SAME ~109MB of
// x lines on every access and every graph replay (fits with ~17MB slack),
// while the other 15% streams. Steady-state DRAM traffic drops from ~220MB
// to ~writes(134MB) + unpinned x(~20MB).
//  - x loads:  createpolicy.fractional.L2::evict_last 0.85 + cache_hint ld.
//  - y stores: __stcs (evict-first), write-once stream stays out of L2.
// Body identical to R4 (best schedule: BLOCK=128, TSTEP=64, group-of-4 MLP).

constexpr int BATCH = 4;
constexpr int SEQ   = 4096;
constexpr int DIM   = 2048;
constexpr int D4    = DIM / 4;      // 512 float4 per (b,t) row
constexpr int TSTEP = 64;           // timesteps per thread
constexpr int BLOCK = 128;

__device__ __forceinline__ unsigned long long mk_evict_last_policy() {
    unsigned long long pol;
    // 85% of lines -> evict_last (pinned), remainder -> evict_unchanged.
    asm("createpolicy.fractional.L2::evict_last.b64 %0, 0.85;" : "=l"(pol));
    return pol;
}

__device__ __forceinline__ float4 ldg_pol(const float4* p, unsigned long long pol) {
    float4 v;
    asm("ld.global.nc.L2::cache_hint.v4.f32 {%0,%1,%2,%3}, [%4], %5;"
        : "=f"(v.x), "=f"(v.y), "=f"(v.z), "=f"(v.w)
        : "l"(p), "l"(pol));
    return v;
}

__global__ void __launch_bounds__(BLOCK, 8)
shortconv1d_kernel(const float4* __restrict__ x4,
                   const float4* __restrict__ w4,   // [D] float4: 4 taps of channel d
                   const float4* __restrict__ b4,   // [D4]
                   float4* __restrict__ y4)
{
    const int d4 = blockIdx.x * BLOCK + threadIdx.x;   // 0..511 (grid.x = 4)
    const int t0 = blockIdx.y * TSTEP;                 // grid.y = SEQ/TSTEP = 64
    const int bb = blockIdx.z;                         // grid.z = 4

    const unsigned long long pol = mk_evict_last_policy();

    // w is [D, K] row-major -> the 4 taps of channel c are the float4 w4[c].
    const int c0 = d4 * 4;
    const float4 wc0 = w4[c0 + 0];
    const float4 wc1 = w4[c0 + 1];
    const float4 wc2 = w4[c0 + 2];
    const float4 wc3 = w4[c0 + 3];
    const float4 bias = b4[d4];

    const float4* xb = x4 + (size_t)bb * SEQ * D4 + d4;
    float4*       yb = y4 + (size_t)bb * SEQ * D4 + d4;

    const float4 zero = make_float4(0.f, 0.f, 0.f, 0.f);

    // Sliding window: h0 = x[t-3], h1 = x[t-2], h2 = x[t-1]
    float4 h0 = (t0 >= 3) ? ldg_pol(&xb[(size_t)(t0 - 3) * D4], pol) : zero;
    float4 h1 = (t0 >= 2) ? ldg_pol(&xb[(size_t)(t0 - 2) * D4], pol) : zero;
    float4 h2 = (t0 >= 1) ? ldg_pol(&xb[(size_t)(t0 - 1) * D4], pol) : zero;

#pragma unroll
    for (int i = 0; i < TSTEP; i += 4) {
        // 4 independent LDG.128 up front (MLP>=4) before the dependent FMAs.
        const float4 cv0 = ldg_pol(&xb[(size_t)(t0 + i + 0) * D4], pol);
        const float4 cv1 = ldg_pol(&xb[(size_t)(t0 + i + 1) * D4], pol);
        const float4 cv2 = ldg_pol(&xb[(size_t)(t0 + i + 2) * D4], pol);
        const float4 cv3 = ldg_pol(&xb[(size_t)(t0 + i + 3) * D4], pol);

        float4 o0;
        o0.x = bias.x + wc0.x * h0.x + wc0.y * h1.x + wc0.z * h2.x + wc0.w * cv0.x;
        o0.y = bias.y + wc1.x * h0.y + wc1.y * h1.y + wc1.z * h2.y + wc1.w * cv0.y;
        o0.z = bias.z + wc2.x * h0.z + wc2.y * h1.z + wc2.z * h2.z + wc2.w * cv0.z;
        o0.w = bias.w + wc3.x * h0.w + wc3.y * h1.w + wc3.z * h2.w + wc3.w * cv0.w;
        __stcs(&yb[(size_t)(t0 + i + 0) * D4], o0);

        float4 o1;
        o1.x = bias.x + wc0.x * h1.x + wc0.y * h2.x + wc0.z * cv0.x + wc0.w * cv1.x;
        o1.y = bias.y + wc1.x * h1.y + wc1.y * h2.y + wc1.z * cv0.y + wc1.w * cv1.y;
        o1.z = bias.z + wc2.x * h1.z + wc2.y * h2.z + wc2.z * cv0.z + wc2.w * cv1.z;
        o1.w = bias.w + wc3.x * h1.w + wc3.y * h2.w + wc3.z * cv0.w + wc3.w * cv1.w;
        __stcs(&yb[(size_t)(t0 + i + 1) * D4], o1);

        float4 o2;
        o2.x = bias.x + wc0.x * h2.x + wc0.y * cv0.x + wc0.z * cv1.x + wc0.w * cv2.x;
        o2.y = bias.y + wc1.x * h2.y + wc1.y * cv0.y + wc1.z * cv1.y + wc1.w * cv2.y;
        o2.z = bias.z + wc2.x * h2.z + wc2.y * cv0.z + wc2.z * cv1.z + wc2.w * cv2.z;
        o2.w = bias.w + wc3.x * h2.w + wc3.y * cv0.w + wc3.z * cv1.w + wc3.w * cv2.w;
        __stcs(&yb[(size_t)(t0 + i + 2) * D4], o2);

        float4 o3;
        o3.x = bias.x + wc0.x * cv0.x + wc0.y * cv1.x + wc0.z * cv2.x + wc0.w * cv3.x;
        o3.y = bias.y + wc1.x * cv0.y + wc1.y * cv1.y + wc1.z * cv2.y + wc1.w * cv3.y;
        o3.z = bias.z + wc2.x * cv0.z + wc2.y * cv1.z + wc2.z * cv2.z + wc2.w * cv3.z;
        o3.w = bias.w + wc3.x * cv0.w + wc3.y * cv1.w + wc3.z * cv2.w + wc3.w * cv3.w;
        __stcs(&yb[(size_t)(t0 + i + 3) * D4], o3);

        h0 = cv1; h1 = cv2; h2 = cv3;
    }
}

extern "C" void kernel_launch(void* const* d_in, const int* in_sizes, int n_in,
                              void* d_out, int out_size)
{
    const float4* x4 = (const float4*)d_in[0];
    const float4* w4 = (const float4*)d_in[1];
    const float4* b4 = (const float4*)d_in[2];
    float4*       y4 = (float4*)d_out;

    dim3 grid(D4 / BLOCK, SEQ / TSTEP, BATCH);
    shortconv1d_kernel<<<grid, BLOCK>>>(x4, w4, b4, y4);
}

// round 16
// speedup vs baseline: 1.0227x; 1.0227x over previous
#include <cuda_runtime.h>

// ShortConv1D: causal depthwise conv1d
// x: [B=4, S=4096, D=2048] f32, w: [D, K=4], b: [D]
// out[b,t,d] = b[d] + sum_k w[d,k] * x[b, t+k-(K-1), d]
//
// Steady-state model (post-R14): full 268MB moves per graph replay; the
// ncu traffic deficit is deferred y writebacks, not cross-replay x reuse.
// At 37.5us we're at ~7.1TB/s effective (~89% of spec) -> hard DRAM-mix
// ceiling. Schedule + cache-hint levers exhausted (7 variants in 37.5-41us).
//
// R15: best-known config (evict_last x loads, __stcs y stores, BLOCK=128,
// TSTEP=64) with the inner loop widened to GROUP-OF-8: 8 independent
// LDG.128 batched before any dependent FMA. ~78 regs -> 6 blocks/SM ->
// 24 warps x 8 outstanding = +50% SM-level lines in flight vs group-of-4.
// If this is neutral, R10's config is final.

constexpr int BATCH = 4;
constexpr int SEQ   = 4096;
constexpr int DIM   = 2048;
constexpr int D4    = DIM / 4;      // 512 float4 per (b,t) row
constexpr int TSTEP = 64;           // timesteps per thread
constexpr int BLOCK = 128;

__device__ __forceinline__ unsigned long long mk_evict_last_policy() {
    unsigned long long pol;
    asm("createpolicy.fractional.L2::evict_last.b64 %0, 1.0;" : "=l"(pol));
    return pol;
}

__device__ __forceinline__ float4 ldg_pol(const float4* p, unsigned long long pol) {
    float4 v;
    asm("ld.global.nc.L2::cache_hint.v4.f32 {%0,%1,%2,%3}, [%4], %5;"
        : "=f"(v.x), "=f"(v.y), "=f"(v.z), "=f"(v.w)
        : "l"(p), "l"(pol));
    return v;
}

__global__ void __launch_bounds__(BLOCK)
shortconv1d_kernel(const float4* __restrict__ x4,
                   const float4* __restrict__ w4,   // [D] float4: 4 taps of channel d
                   const float4* __restrict__ b4,   // [D4]
                   float4* __restrict__ y4)
{
    const int d4 = blockIdx.x * BLOCK + threadIdx.x;   // 0..511 (grid.x = 4)
    const int t0 = blockIdx.y * TSTEP;                 // grid.y = SEQ/TSTEP = 64
    const int bb = blockIdx.z;                         // grid.z = 4

    const unsigned long long pol = mk_evict_last_policy();

    // w is [D, K] row-major -> the 4 taps of channel c are the float4 w4[c].
    const int c0 = d4 * 4;
    const float4 wc0 = w4[c0 + 0];
    const float4 wc1 = w4[c0 + 1];
    const float4 wc2 = w4[c0 + 2];
    const float4 wc3 = w4[c0 + 3];
    const float4 bias = b4[d4];

    const float4* xb = x4 + (size_t)bb * SEQ * D4 + d4;
    float4*       yb = y4 + (size_t)bb * SEQ * D4 + d4;

    const float4 zero = make_float4(0.f, 0.f, 0.f, 0.f);

    // Sliding window: h0 = x[t-3], h1 = x[t-2], h2 = x[t-1]
    float4 h0 = (t0 >= 3) ? ldg_pol(&xb[(size_t)(t0 - 3) * D4], pol) : zero;
    float4 h1 = (t0 >= 2) ? ldg_pol(&xb[(size_t)(t0 - 2) * D4], pol) : zero;
    float4 h2 = (t0 >= 1) ? ldg_pol(&xb[(size_t)(t0 - 1) * D4], pol) : zero;

#pragma unroll
    for (int i = 0; i < TSTEP; i += 8) {
        // 8 independent LDG.128 batched up front: per-warp MLP ~8 before the
        // dependent FMA/STG chain consumes anything.
        float4 cv[8];
#pragma unroll
        for (int j = 0; j < 8; j++)
            cv[j] = ldg_pol(&xb[(size_t)(t0 + i + j) * D4], pol);

        // t = i+0 .. i+2 use the carried window
        float4 o;
        o.x = bias.x + wc0.x * h0.x + wc0.y * h1.x + wc0.z * h2.x + wc0.w * cv[0].x;
        o.y = bias.y + wc1.x * h0.y + wc1.y * h1.y + wc1.z * h2.y + wc1.w * cv[0].y;
        o.z = bias.z + wc2.x * h0.z + wc2.y * h1.z + wc2.z * h2.z + wc2.w * cv[0].z;
        o.w = bias.w + wc3.x * h0.w + wc3.y * h1.w + wc3.z * h2.w + wc3.w * cv[0].w;
        __stcs(&yb[(size_t)(t0 + i + 0) * D4], o);

        o.x = bias.x + wc0.x * h1.x + wc0.y * h2.x + wc0.z * cv[0].x + wc0.w * cv[1].x;
        o.y = bias.y + wc1.x * h1.y + wc1.y * h2.y + wc1.z * cv[0].y + wc1.w * cv[1].y;
        o.z = bias.z + wc2.x * h1.z + wc2.y * h2.z + wc2.z * cv[0].z + wc2.w * cv[1].z;
        o.w = bias.w + wc3.x * h1.w + wc3.y * h2.w + wc3.z * cv[0].w + wc3.w * cv[1].w;
        __stcs(&yb[(size_t)(t0 + i + 1) * D4], o);

        o.x = bias.x + wc0.x * h2.x + wc0.y * cv[0].x + wc0.z * cv[1].x + wc0.w * cv[2].x;
        o.y = bias.y + wc1.x * h2.y + wc1.y * cv[0].y + wc1.z * cv[1].y + wc1.w * cv[2].y;
        o.z = bias.z + wc2.x * h2.z + wc2.y * cv[0].z + wc2.z * cv[1].z + wc2.w * cv[2].z;
        o.w = bias.w + wc3.x * h2.w + wc3.y * cv[0].w + wc3.z * cv[1].w + wc3.w * cv[2].w;
        __stcs(&yb[(size_t)(t0 + i + 2) * D4], o);

        // t = i+3 .. i+7 use only this group's loads
#pragma unroll
        for (int j = 3; j < 8; j++) {
            o.x = bias.x + wc0.x * cv[j-3].x + wc0.y * cv[j-2].x + wc0.z * cv[j-1].x + wc0.w * cv[j].x;
            o.y = bias.y + wc1.x * cv[j-3].y + wc1.y * cv[j-2].y + wc1.z * cv[j-1].y + wc1.w * cv[j].y;
            o.z = bias.z + wc2.x * cv[j-3].z + wc2.y * cv[j-2].z + wc2.z * cv[j-1].z + wc2.w * cv[j].z;
            o.w = bias.w + wc3.x * cv[j-3].w + wc3.y * cv[j-2].w + wc3.z * cv[j-1].w + wc3.w * cv[j].w;
            __stcs(&yb[(size_t)(t0 + i + j) * D4], o);
        }

        h0 = cv[5]; h1 = cv[6]; h2 = cv[7];
    }
}

extern "C" void kernel_launch(void* const* d_in, const int* in_sizes, int n_in,
                              void* d_out, int out_size)
{
    const float4* x4 = (const float4*)d_in[0];
    const float4* w4 = (const float4*)d_in[1];
    const float4* b4 = (const float4*)d_in[2];
    float4*       y4 = (float4*)d_out;

    dim3 grid(D4 / BLOCK, SEQ / TSTEP, BATCH);
    shortconv1d_kernel<<<grid, BLOCK>>>(x4, w4, b4, y4);
}

// round 17
// speedup vs baseline: 1.0282x; 1.0054x over previous
#include <cuda_runtime.h>

// ShortConv1D: causal depthwise conv1d — FINAL (= R10, measured best).
// x: [B=4, S=4096, D=2048] f32, w: [D, K=4], b: [D]
// out[b,t,d] = b[d] + sum_k w[d,k] * x[b, t+k-(K-1), d]
//
// Conclusion after 8 profiled variants (37.5-41us): the kernel sits at the
// DRAM-controller ceiling for a 1:1 R/W mix. 268MB moves per replay; at
// 37.5us that's ~7.1TB/s effective (~89% of 8TB/s spec). Occupancy, MLP,
// wave shaping, prefetch, and all L2 policies are exhausted; traffic is
// within 4.7% of mandatory. This config measured fastest (37.5us kernel):
//  - BLOCK=128, TSTEP=64: single wave (1024 blocks @ 8/SM), halo amp 67/64.
//  - group-of-4 inner loop: 4 independent LDG.128 before dependent FMAs.
//  - x loads: evict_last policy (best of the hint sweep).
//  - y stores: __stcs (write-once stream, evict-first).

constexpr int BATCH = 4;
constexpr int SEQ   = 4096;
constexpr int DIM   = 2048;
constexpr int D4    = DIM / 4;      // 512 float4 per (b,t) row
constexpr int TSTEP = 64;           // timesteps per thread
constexpr int BLOCK = 128;

__device__ __forceinline__ unsigned long long mk_evict_last_policy() {
    unsigned long long pol;
    asm("createpolicy.fractional.L2::evict_last.b64 %0, 1.0;" : "=l"(pol));
    return pol;
}

__device__ __forceinline__ float4 ldg_pol(const float4* p, unsigned long long pol) {
    float4 v;
    asm("ld.global.nc.L2::cache_hint.v4.f32 {%0,%1,%2,%3}, [%4], %5;"
        : "=f"(v.x), "=f"(v.y), "=f"(v.z), "=f"(v.w)
        : "l"(p), "l"(pol));
    return v;
}

__global__ void __launch_bounds__(BLOCK, 8)
shortconv1d_kernel(const float4* __restrict__ x4,
                   const float4* __restrict__ w4,   // [D] float4: 4 taps of channel d
                   const float4* __restrict__ b4,   // [D4]
                   float4* __restrict__ y4)
{
    const int d4 = blockIdx.x * BLOCK + threadIdx.x;   // 0..511 (grid.x = 4)
    const int t0 = blockIdx.y * TSTEP;                 // grid.y = SEQ/TSTEP = 64
    const int bb = blockIdx.z;                         // grid.z = 4

    const unsigned long long pol = mk_evict_last_policy();

    // w is [D, K] row-major -> the 4 taps of channel c are the float4 w4[c].
    const int c0 = d4 * 4;
    const float4 wc0 = w4[c0 + 0];
    const float4 wc1 = w4[c0 + 1];
    const float4 wc2 = w4[c0 + 2];
    const float4 wc3 = w4[c0 + 3];
    const float4 bias = b4[d4];

    const float4* xb = x4 + (size_t)bb * SEQ * D4 + d4;
    float4*       yb = y4 + (size_t)bb * SEQ * D4 + d4;

    const float4 zero = make_float4(0.f, 0.f, 0.f, 0.f);

    // Sliding window: h0 = x[t-3], h1 = x[t-2], h2 = x[t-1]
    float4 h0 = (t0 >= 3) ? ldg_pol(&xb[(size_t)(t0 - 3) * D4], pol) : zero;
    float4 h1 = (t0 >= 2) ? ldg_pol(&xb[(size_t)(t0 - 2) * D4], pol) : zero;
    float4 h2 = (t0 >= 1) ? ldg_pol(&xb[(size_t)(t0 - 1) * D4], pol) : zero;

#pragma unroll
    for (int i = 0; i < TSTEP; i += 4) {
        // 4 independent LDG.128 up front (MLP>=4) before the dependent FMAs.
        const float4 cv0 = ldg_pol(&xb[(size_t)(t0 + i + 0) * D4], pol);
        const float4 cv1 = ldg_pol(&xb[(size_t)(t0 + i + 1) * D4], pol);
        const float4 cv2 = ldg_pol(&xb[(size_t)(t0 + i + 2) * D4], pol);
        const float4 cv3 = ldg_pol(&xb[(size_t)(t0 + i + 3) * D4], pol);

        float4 o0;
        o0.x = bias.x + wc0.x * h0.x + wc0.y * h1.x + wc0.z * h2.x + wc0.w * cv0.x;
        o0.y = bias.y + wc1.x * h0.y + wc1.y * h1.y + wc1.z * h2.y + wc1.w * cv0.y;
        o0.z = bias.z + wc2.x * h0.z + wc2.y * h1.z + wc2.z * h2.z + wc2.w * cv0.z;
        o0.w = bias.w + wc3.x * h0.w + wc3.y * h1.w + wc3.z * h2.w + wc3.w * cv0.w;
        __stcs(&yb[(size_t)(t0 + i + 0) * D4], o0);

        float4 o1;
        o1.x = bias.x + wc0.x * h1.x + wc0.y * h2.x + wc0.z * cv0.x + wc0.w * cv1.x;
        o1.y = bias.y + wc1.x * h1.y + wc1.y * h2.y + wc1.z * cv0.y + wc1.w * cv1.y;
        o1.z = bias.z + wc2.x * h1.z + wc2.y * h2.z + wc2.z * cv0.z + wc2.w * cv1.z;
        o1.w = bias.w + wc3.x * h1.w + wc3.y * h2.w + wc3.z * cv0.w + wc3.w * cv1.w;
        __stcs(&yb[(size_t)(t0 + i + 1) * D4], o1);

        float4 o2;
        o2.x = bias.x + wc0.x * h2.x + wc0.y * cv0.x + wc0.z * cv1.x + wc0.w * cv2.x;
        o2.y = bias.y + wc1.x * h2.y + wc1.y * cv0.y + wc1.z * cv1.y + wc1.w * cv2.y;
        o2.z = bias.z + wc2.x * h2.z + wc2.y * cv0.z + wc2.z * cv1.z + wc2.w * cv2.z;
        o2.w = bias.w + wc3.x * h2.w + wc3.y * cv0.w + wc3.z * cv1.w + wc3.w * cv2.w;
        __stcs(&yb[(size_t)(t0 + i + 2) * D4], o2);

        float4 o3;
        o3.x = bias.x + wc0.x * cv0.x + wc0.y * cv1.x + wc0.z * cv2.x + wc0.w * cv3.x;
        o3.y = bias.y + wc1.x * cv0.y + wc1.y * cv1.y + wc1.z * cv2.y + wc1.w * cv3.y;
        o3.z = bias.z + wc2.x * cv0.z + wc2.y * cv1.z + wc2.z * cv2.z + wc2.w * cv3.z;
        o3.w = bias.w + wc3.x * cv0.w + wc3.y * cv1.w + wc3.z * cv2.w + wc3.w * cv3.w;
        __stcs(&yb[(size_t)(t0 + i + 3) * D4], o3);

        h0 = cv1; h1 = cv2; h2 = cv3;
    }
}

extern "C" void kernel_launch(void* const* d_in, const int* in_sizes, int n_in,
                              void* d_out, int out_size)
{
    const float4* x4 = (const float4*)d_in[0];
    const float4* w4 = (const float4*)d_in[1];
    const float4* b4 = (const float4*)d_in[2];
    float4*       y4 = (float4*)d_out;

    dim3 grid(D4 / BLOCK, SEQ / TSTEP, BATCH);
    shortconv1d_kernel<<<grid, BLOCK>>>(x4, w4, b4, y4);
}